// round 4
// baseline (speedup 1.0000x reference)
#include <cuda_runtime.h>
#include <cstdint>

// Problem constants
#define NB 16
#define NG 64
#define NS 4096
#define NC 384
#define NH 6
#define ND 64

// fp32 helper-GEMM tile config (K1/K4, small)
#define BM 128
#define BN 64
#define BK 16
#define AP 132
#define BP2 68

// tf32 GEMM smem pitch
#define PA 20

// Scratch
__device__ __align__(16) float g_qT[NB * NH * ND * NG];   // q^T: [b][h][d][n]
__device__ __align__(16) float g_acc[NB * NH * NG * ND];
__device__ int   g_cnt[NB * NH * NG];

// ---------------------------------------------------------------------------
// tf32 helpers
// ---------------------------------------------------------------------------
__device__ __forceinline__ uint32_t f2tf(float x) {
    uint32_t u;
    asm("cvt.rna.tf32.f32 %0, %1;" : "=r"(u) : "f"(x));
    return u;
}

__device__ __forceinline__ void mma_tf32(float c[4], const uint32_t a[4],
                                         const uint32_t b[2]) {
    asm volatile(
        "mma.sync.aligned.m16n8k8.row.col.f32.tf32.tf32.f32 "
        "{%0,%1,%2,%3}, {%4,%5,%6,%7}, {%8,%9}, {%0,%1,%2,%3};"
        : "+f"(c[0]), "+f"(c[1]), "+f"(c[2]), "+f"(c[3])
        : "r"(a[0]), "r"(a[1]), "r"(a[2]), "r"(a[3]), "r"(b[0]), "r"(b[1]));
}

template <bool SPLIT>
__device__ __forceinline__ void sts_split(float* hi, float* lo, int off, float4 v) {
    float x[4] = {v.x, v.y, v.z, v.w};
#pragma unroll
    for (int j = 0; j < 4; ++j) {
        uint32_t h = f2tf(x[j]);
        hi[off + j] = __uint_as_float(h);
        if (SPLIT)
            lo[off + j] = __uint_as_float(f2tf(x[j] - __uint_as_float(h)));
    }
}

// ---------------------------------------------------------------------------
// fp32 helper GEMM pieces (K1 / K4 — small)
// ---------------------------------------------------------------------------
__device__ __forceinline__ void load_A_tile(const float* __restrict__ A,
                                            int mBase, int k0, float* As, int tid) {
#pragma unroll
    for (int l = 0; l < 2; ++l) {
        int lin = tid * 2 + l;
        int m = lin >> 2;
        int kg = (lin & 3) * 4;
        float4 v = *(const float4*)(A + (size_t)(mBase + m) * NC + k0 + kg);
        As[(kg + 0) * AP + m] = v.x;
        As[(kg + 1) * AP + m] = v.y;
        As[(kg + 2) * AP + m] = v.z;
        As[(kg + 3) * AP + m] = v.w;
    }
}

__device__ __forceinline__ void load_B_tile(const float* __restrict__ W,
                                            int nBase, int k0, float* Bs, int tid) {
    int wr = tid >> 2;
    int kg = (tid & 3) * 4;
    float4 v = *(const float4*)(W + (size_t)(nBase + wr) * NC + k0 + kg);
    Bs[(kg + 0) * BP2 + wr] = v.x;
    Bs[(kg + 1) * BP2 + wr] = v.y;
    Bs[(kg + 2) * BP2 + wr] = v.z;
    Bs[(kg + 3) * BP2 + wr] = v.w;
}

__device__ __forceinline__ void mma_tile(const float* As, const float* Bs,
                                         float c[8][4], int trow, int tcol) {
#pragma unroll
    for (int k = 0; k < BK; ++k) {
        float4 a0 = *(const float4*)(As + k * AP + trow * 8);
        float4 a1 = *(const float4*)(As + k * AP + trow * 8 + 4);
        float4 b0 = *(const float4*)(Bs + k * BP2 + tcol * 4);
        float a[8] = {a0.x, a0.y, a0.z, a0.w, a1.x, a1.y, a1.z, a1.w};
        float b[4] = {b0.x, b0.y, b0.z, b0.w};
#pragma unroll
        for (int i = 0; i < 8; ++i)
#pragma unroll
            for (int j = 0; j < 4; ++j)
                c[i][j] += a[i] * b[j];
    }
}

// ---------------------------------------------------------------------------
// K0: zero accumulators
// ---------------------------------------------------------------------------
__global__ void k_zero() {
    int i = blockIdx.x * blockDim.x + threadIdx.x;
    if (i < NB * NH * NG * ND) g_acc[i] = 0.0f;
    if (i < NB * NH * NG) g_cnt[i] = 0;
}

// ---------------------------------------------------------------------------
// K1: q projection -> g_qT[b][h][d][n] (fp32, tiny)
// ---------------------------------------------------------------------------
__global__ void __launch_bounds__(256) k_qproj(const float* __restrict__ query,
                                               const float* __restrict__ Wq) {
    __shared__ float As[BK * AP];
    __shared__ float Bs[BK * BP2];
    int tid = threadIdx.x;
    int trow = tid >> 4, tcol = tid & 15;
    int mBase = blockIdx.x * BM;
    int h = blockIdx.y;

    float c[8][4] = {};
    for (int k0 = 0; k0 < NC; k0 += BK) {
        load_A_tile(query, mBase, k0, As, tid);
        load_B_tile(Wq, h * 64, k0, Bs, tid);
        __syncthreads();
        mma_tile(As, Bs, c, trow, tcol);
        __syncthreads();
    }
#pragma unroll
    for (int i = 0; i < 8; ++i) {
        int m = mBase + trow * 8 + i;
        int b = m >> 6, n = m & 63;
#pragma unroll
        for (int j = 0; j < 4; ++j) {
            int d = tcol * 4 + j;
            g_qT[((b * NH + h) * ND + d) * NG + n] = c[i][j];
        }
    }
}

// ---------------------------------------------------------------------------
// K23 fused: one pass over key tiles computing BOTH
//   scores (3xTF32, fp32-accurate) -> argmax -> block-local idx
//   vp     (1xTF32)                -> atomic scatter using local idx
// ---------------------------------------------------------------------------
__global__ void __launch_bounds__(256) k23_fused(const float* __restrict__ key,
                                                 const float* __restrict__ Wk,
                                                 const float* __restrict__ Wv) {
    __shared__ __align__(16) union {
        struct {
            float Ah[128 * PA]; float Al[128 * PA];
            float Bkh[64 * PA]; float Bkl[64 * PA]; float Bvh[64 * PA];
        } g;                                   // 35840 B
        struct { float Kp[128 * 64]; float Qs[32 * 64]; } e;  // 40960 B
    } sm;
    __shared__ int sIdx[128];

    int tid = threadIdx.x;
    int lane = tid & 31;
    int warpM = (tid >> 5) & 3;
    int warpN = tid >> 7;
    int grp = lane >> 2, qd = lane & 3;

    int mBase = blockIdx.x * 128;
    int b = mBase >> 12;
    int h = blockIdx.y;
    int bh = b * NH + h;

    const float* WkH = Wk + (size_t)h * 64 * NC;
    const float* WvH = Wv + (size_t)h * 64 * NC;

    float cs[2][4][4] = {};   // scores accum
    float cv[2][4][4] = {};   // v accum

    int am0 = tid >> 2;               // 0..63
    int ak = (tid & 3) * 4;
    const float* pa0 = key + (size_t)(mBase + am0) * NC + ak;
    const float* pa1 = pa0 + (size_t)64 * NC;
    const float* pbk = WkH + (size_t)am0 * NC + ak;
    const float* pbv = WvH + (size_t)am0 * NC + ak;

    float4 ra0 = *(const float4*)pa0;
    float4 ra1 = *(const float4*)pa1;
    float4 rbk = *(const float4*)pbk;
    float4 rbv = *(const float4*)pbv;

    for (int kt = 0; kt < NC / 16; ++kt) {
        __syncthreads();
        sts_split<true >(sm.g.Ah,  sm.g.Al,  am0 * PA + ak, ra0);
        sts_split<true >(sm.g.Ah,  sm.g.Al,  (am0 + 64) * PA + ak, ra1);
        sts_split<true >(sm.g.Bkh, sm.g.Bkl, am0 * PA + ak, rbk);
        sts_split<false>(sm.g.Bvh, nullptr,  am0 * PA + ak, rbv);
        __syncthreads();
        if (kt < NC / 16 - 1) {
            int k0 = (kt + 1) * 16;
            ra0 = *(const float4*)(pa0 + k0);
            ra1 = *(const float4*)(pa1 + k0);
            rbk = *(const float4*)(pbk + k0);
            rbv = *(const float4*)(pbv + k0);
        }
#pragma unroll
        for (int kk = 0; kk < 16; kk += 8) {
            uint32_t ah[2][4], al[2][4], bkh[4][2], bkl[4][2], bvh[4][2];
#pragma unroll
            for (int mi = 0; mi < 2; ++mi) {
                int r = warpM * 32 + mi * 16 + grp;
                const float* ph = sm.g.Ah + r * PA + kk + qd;
                const float* pl = sm.g.Al + r * PA + kk + qd;
                ah[mi][0] = __float_as_uint(ph[0]);
                ah[mi][1] = __float_as_uint(ph[8 * PA]);
                ah[mi][2] = __float_as_uint(ph[4]);
                ah[mi][3] = __float_as_uint(ph[8 * PA + 4]);
                al[mi][0] = __float_as_uint(pl[0]);
                al[mi][1] = __float_as_uint(pl[8 * PA]);
                al[mi][2] = __float_as_uint(pl[4]);
                al[mi][3] = __float_as_uint(pl[8 * PA + 4]);
            }
#pragma unroll
            for (int nj = 0; nj < 4; ++nj) {
                int cn = warpN * 32 + nj * 8 + grp;
                const float* pkh = sm.g.Bkh + cn * PA + kk + qd;
                const float* pkl = sm.g.Bkl + cn * PA + kk + qd;
                const float* pvh = sm.g.Bvh + cn * PA + kk + qd;
                bkh[nj][0] = __float_as_uint(pkh[0]);
                bkh[nj][1] = __float_as_uint(pkh[4]);
                bkl[nj][0] = __float_as_uint(pkl[0]);
                bkl[nj][1] = __float_as_uint(pkl[4]);
                bvh[nj][0] = __float_as_uint(pvh[0]);
                bvh[nj][1] = __float_as_uint(pvh[4]);
            }
#pragma unroll
            for (int mi = 0; mi < 2; ++mi)
#pragma unroll
                for (int nj = 0; nj < 4; ++nj) {
                    mma_tf32(cs[mi][nj], al[mi], bkh[nj]);
                    mma_tf32(cs[mi][nj], ah[mi], bkl[nj]);
                    mma_tf32(cs[mi][nj], ah[mi], bkh[nj]);
                    mma_tf32(cv[mi][nj], ah[mi], bvh[nj]);
                }
        }
    }

    __syncthreads();  // GEMM smem reads done before union repurpose

    // Stage kp (scores operand) to smem [s][d]
#pragma unroll
    for (int mi = 0; mi < 2; ++mi)
#pragma unroll
        for (int nj = 0; nj < 4; ++nj) {
            int row = warpM * 32 + mi * 16 + grp;
            int col = warpN * 32 + nj * 8 + 2 * qd;
            *(float2*)&sm.e.Kp[row * 64 + col] =
                make_float2(cs[mi][nj][0], cs[mi][nj][1]);
            *(float2*)&sm.e.Kp[(row + 8) * 64 + col] =
                make_float2(cs[mi][nj][2], cs[mi][nj][3]);
        }

    // scores[128 s][64 n] = Kp @ qT, q loaded in two 32-d halves
    int tr = tid >> 4, tc = tid & 15;
    float acc2[8][4] = {};
    const float* qsrc = g_qT + (size_t)bh * ND * NG;
#pragma unroll
    for (int dh = 0; dh < 2; ++dh) {
        if (dh) __syncthreads();  // prior half's Qs reads complete
        {
            int off = tid * 8;
            *(float4*)&sm.e.Qs[off]     = *(const float4*)&qsrc[dh * 32 * NG + off];
            *(float4*)&sm.e.Qs[off + 4] = *(const float4*)&qsrc[dh * 32 * NG + off + 4];
        }
        __syncthreads();
#pragma unroll 8
        for (int dl = 0; dl < 32; ++dl) {
            float4 q4 = *(const float4*)&sm.e.Qs[dl * 64 + tc * 4];
#pragma unroll
            for (int i = 0; i < 8; ++i) {
                float a = sm.e.Kp[(tr * 8 + i) * 64 + dh * 32 + dl];
                acc2[i][0] += a * q4.x;
                acc2[i][1] += a * q4.y;
                acc2[i][2] += a * q4.z;
                acc2[i][3] += a * q4.w;
            }
        }
    }

    // argmax over n per key row -> block-local sIdx + global counts
#pragma unroll
    for (int i = 0; i < 8; ++i) {
        float mv = acc2[i][0];
        int mi = tc * 4;
#pragma unroll
        for (int j = 1; j < 4; ++j)
            if (acc2[i][j] > mv) { mv = acc2[i][j]; mi = tc * 4 + j; }
#pragma unroll
        for (int off = 8; off >= 1; off >>= 1) {
            float ov = __shfl_down_sync(0xffffffffu, mv, off, 16);
            int   oi = __shfl_down_sync(0xffffffffu, mi, off, 16);
            if (ov > mv || (ov == mv && oi < mi)) { mv = ov; mi = oi; }
        }
        if (tc == 0) {
            sIdx[tr * 8 + i] = mi;
            atomicAdd(&g_cnt[bh * NG + mi], 1);
        }
    }
    __syncthreads();

    // scatter vp using local idx
#pragma unroll
    for (int mi = 0; mi < 2; ++mi) {
        int r0 = warpM * 32 + mi * 16 + grp;
        int n0 = sIdx[r0];
        int n1 = sIdx[r0 + 8];
#pragma unroll
        for (int nj = 0; nj < 4; ++nj) {
            int d = warpN * 32 + nj * 8 + 2 * qd;
            float* p0 = &g_acc[(bh * NG + n0) * ND + d];
            atomicAdd(p0,     cv[mi][nj][0]);
            atomicAdd(p0 + 1, cv[mi][nj][1]);
            float* p1 = &g_acc[(bh * NG + n1) * ND + d];
            atomicAdd(p1,     cv[mi][nj][2]);
            atomicAdd(p1 + 1, cv[mi][nj][3]);
        }
    }
}

// ---------------------------------------------------------------------------
// K4: normalize + out = tmp @ Wp^T + bp (fp32, tiny)
// ---------------------------------------------------------------------------
__global__ void __launch_bounds__(256) k_finalize(const float* __restrict__ Wp,
                                                  const float* __restrict__ bp,
                                                  float* __restrict__ out) {
    __shared__ float As[BK * AP];
    __shared__ float Bs[BK * BP2];
    int tid = threadIdx.x;
    int trow = tid >> 4, tcol = tid & 15;
    int mBase = blockIdx.x * BM;
    int nBase = blockIdx.y * BN;

    float c[8][4] = {};
    for (int k0 = 0; k0 < NC; k0 += BK) {
#pragma unroll
        for (int l = 0; l < 2; ++l) {
            int lin = tid * 2 + l;
            int m = lin >> 2;
            int kg = (lin & 3) * 4;
            int gm = mBase + m;
            int b = gm >> 6, n = gm & 63;
            int cc = k0 + kg;
            int h = cc >> 6, d = cc & 63;
            int bh = b * NH + h;
            float inv = 1.0f / (float)(g_cnt[bh * NG + n] + 1);
            float4 v = *(const float4*)&g_acc[(bh * NG + n) * ND + d];
            As[(kg + 0) * AP + m] = v.x * inv;
            As[(kg + 1) * AP + m] = v.y * inv;
            As[(kg + 2) * AP + m] = v.z * inv;
            As[(kg + 3) * AP + m] = v.w * inv;
        }
        load_B_tile(Wp, nBase, k0, Bs, tid);
        __syncthreads();
        mma_tile(As, Bs, c, trow, tcol);
        __syncthreads();
    }

    float4 bias = *(const float4*)&bp[nBase + tcol * 4];
#pragma unroll
    for (int i = 0; i < 8; ++i) {
        int m = mBase + trow * 8 + i;
        float4 v = make_float4(c[i][0] + bias.x, c[i][1] + bias.y,
                               c[i][2] + bias.z, c[i][3] + bias.w);
        *(float4*)&out[(size_t)m * NC + nBase + tcol * 4] = v;
    }
}

// ---------------------------------------------------------------------------
extern "C" void kernel_launch(void* const* d_in, const int* in_sizes, int n_in,
                              void* d_out, int out_size) {
    const float* query = (const float*)d_in[0];
    const float* key   = (const float*)d_in[1];
    const float* Wq    = (const float*)d_in[2];
    const float* Wk    = (const float*)d_in[3];
    const float* Wv    = (const float*)d_in[4];
    const float* Wp    = (const float*)d_in[5];
    const float* bp    = (const float*)d_in[6];
    float* out = (float*)d_out;

    k_zero<<<(NB * NH * NG * ND + 255) / 256, 256>>>();
    k_qproj<<<dim3(8, 6), 256>>>(query, Wq);
    k23_fused<<<dim3((NB * NS) / 128, NH), 256>>>(key, Wk, Wv);
    k_finalize<<<dim3(8, 6), 256>>>(Wp, bp, out);
}

// round 7
// speedup vs baseline: 1.0535x; 1.0535x over previous
#include <cuda_runtime.h>
#include <cstdint>

// Problem constants
#define NB 16
#define NG 64
#define NS 4096
#define NC 384
#define NH 6
#define ND 64

// fp32 helper-GEMM tile config (K1/K4, small)
#define BM 128
#define BN 64
#define BK 16
#define AP 132
#define BP2 68

// tf32 GEMM smem pitch
#define PA 20
#define ASZ (128 * PA)
#define BSZ (64 * PA)

// Scratch
__device__ __align__(16) float g_qT[NB * NH * ND * NG];   // q^T: [bh][d][n]
__device__ int   g_idx[NB * NH * NS];
__device__ __align__(16) float g_acc[NB * NH * NG * ND];
__device__ int   g_cnt[NB * NH * NG];

// ---------------------------------------------------------------------------
// tf32 helpers
// ---------------------------------------------------------------------------
__device__ __forceinline__ uint32_t f2tf(float x) {
    uint32_t u;
    asm("cvt.rna.tf32.f32 %0, %1;" : "=r"(u) : "f"(x));
    return u;
}

__device__ __forceinline__ void mma_tf32(float c[4], const uint32_t a[4],
                                         const uint32_t b[2]) {
    asm volatile(
        "mma.sync.aligned.m16n8k8.row.col.f32.tf32.tf32.f32 "
        "{%0,%1,%2,%3}, {%4,%5,%6,%7}, {%8,%9}, {%0,%1,%2,%3};"
        : "+f"(c[0]), "+f"(c[1]), "+f"(c[2]), "+f"(c[3])
        : "r"(a[0]), "r"(a[1]), "r"(a[2]), "r"(a[3]), "r"(b[0]), "r"(b[1]));
}

template <bool SPLIT>
__device__ __forceinline__ void sts_split(float* hi, float* lo, int off, float4 v) {
    float x[4] = {v.x, v.y, v.z, v.w};
#pragma unroll
    for (int j = 0; j < 4; ++j) {
        uint32_t h = f2tf(x[j]);
        hi[off + j] = __uint_as_float(h);
        if (SPLIT)
            lo[off + j] = __uint_as_float(f2tf(x[j] - __uint_as_float(h)));
    }
}

// ---------------------------------------------------------------------------
// Pipelined 128x64 tf32 GEMM core (2-stage double buffer, 1 sync per tile).
// Arithmetic (MMA sequence/order) identical to the unpipelined R3 version.
// SPLIT=true: 3xTF32 (fp32-accurate). SPLIT=false: 1xTF32.
// ---------------------------------------------------------------------------
template <bool SPLIT>
__device__ __forceinline__ void gemm_tf32_pipe(
    const float* __restrict__ A, const float* __restrict__ W, int mBase,
    float c[2][4][4], float* AhB, float* AlB, float* BhB, float* BlB, int tid) {
    int lane = tid & 31;
    int warpM = (tid >> 5) & 3;
    int warpN = tid >> 7;
    int grp = lane >> 2, qd = lane & 3;

    int am0 = tid >> 2;               // 0..63
    int ak = (tid & 3) * 4;
    const float* pa0 = A + (size_t)(mBase + am0) * NC + ak;
    const float* pa1 = pa0 + (size_t)64 * NC;
    const float* pb  = W + (size_t)am0 * NC + ak;

    // prologue: tile 0 -> stage 0, prefetch tile 1
    float4 ra0 = *(const float4*)pa0;
    float4 ra1 = *(const float4*)pa1;
    float4 rb  = *(const float4*)pb;
    sts_split<SPLIT>(AhB, AlB, am0 * PA + ak, ra0);
    sts_split<SPLIT>(AhB, AlB, (am0 + 64) * PA + ak, ra1);
    sts_split<SPLIT>(BhB, BlB, am0 * PA + ak, rb);
    ra0 = *(const float4*)(pa0 + 16);
    ra1 = *(const float4*)(pa1 + 16);
    rb  = *(const float4*)(pb + 16);

#pragma unroll 1
    for (int kt = 0; kt < NC / 16; ++kt) {
        __syncthreads();
        int cur = kt & 1;
        const float* Ah = AhB + cur * ASZ;
        const float* Al = AlB + cur * ASZ;
        const float* Bh = BhB + cur * BSZ;
        const float* Bl = BlB + cur * BSZ;
        if (kt + 1 < NC / 16) {
            int nxt = (1 - cur);
            sts_split<SPLIT>(AhB + nxt * ASZ, AlB + nxt * ASZ, am0 * PA + ak, ra0);
            sts_split<SPLIT>(AhB + nxt * ASZ, AlB + nxt * ASZ, (am0 + 64) * PA + ak, ra1);
            sts_split<SPLIT>(BhB + nxt * BSZ, BlB + nxt * BSZ, am0 * PA + ak, rb);
        }
        if (kt + 2 < NC / 16) {
            int k0 = (kt + 2) * 16;
            ra0 = *(const float4*)(pa0 + k0);
            ra1 = *(const float4*)(pa1 + k0);
            rb  = *(const float4*)(pb + k0);
        }
#pragma unroll
        for (int kk = 0; kk < 16; kk += 8) {
            uint32_t ah[2][4], al[2][4], bhf[4][2], blf[4][2];
#pragma unroll
            for (int mi = 0; mi < 2; ++mi) {
                int r = warpM * 32 + mi * 16 + grp;
                const float* ph = Ah + r * PA + kk + qd;
                ah[mi][0] = __float_as_uint(ph[0]);
                ah[mi][1] = __float_as_uint(ph[8 * PA]);
                ah[mi][2] = __float_as_uint(ph[4]);
                ah[mi][3] = __float_as_uint(ph[8 * PA + 4]);
                if (SPLIT) {
                    const float* pl = Al + r * PA + kk + qd;
                    al[mi][0] = __float_as_uint(pl[0]);
                    al[mi][1] = __float_as_uint(pl[8 * PA]);
                    al[mi][2] = __float_as_uint(pl[4]);
                    al[mi][3] = __float_as_uint(pl[8 * PA + 4]);
                }
            }
#pragma unroll
            for (int nj = 0; nj < 4; ++nj) {
                int cn = warpN * 32 + nj * 8 + grp;
                const float* pkh = Bh + cn * PA + kk + qd;
                bhf[nj][0] = __float_as_uint(pkh[0]);
                bhf[nj][1] = __float_as_uint(pkh[4]);
                if (SPLIT) {
                    const float* pkl = Bl + cn * PA + kk + qd;
                    blf[nj][0] = __float_as_uint(pkl[0]);
                    blf[nj][1] = __float_as_uint(pkl[4]);
                }
            }
#pragma unroll
            for (int mi = 0; mi < 2; ++mi)
#pragma unroll
                for (int nj = 0; nj < 4; ++nj) {
                    if (SPLIT) {
                        mma_tf32(c[mi][nj], al[mi], bhf[nj]);
                        mma_tf32(c[mi][nj], ah[mi], blf[nj]);
                    }
                    mma_tf32(c[mi][nj], ah[mi], bhf[nj]);
                }
        }
    }
}

// ---------------------------------------------------------------------------
// fp32 helper GEMM pieces (K1 / K4)
// ---------------------------------------------------------------------------
__device__ __forceinline__ void load_A_tile(const float* __restrict__ A,
                                            int mBase, int k0, float* As, int tid) {
#pragma unroll
    for (int l = 0; l < 2; ++l) {
        int lin = tid * 2 + l;
        int m = lin >> 2;
        int kg = (lin & 3) * 4;
        float4 v = *(const float4*)(A + (size_t)(mBase + m) * NC + k0 + kg);
        As[(kg + 0) * AP + m] = v.x;
        As[(kg + 1) * AP + m] = v.y;
        As[(kg + 2) * AP + m] = v.z;
        As[(kg + 3) * AP + m] = v.w;
    }
}

__device__ __forceinline__ void load_B_tile(const float* __restrict__ W,
                                            int nBase, int k0, float* Bs, int tid) {
    int wr = tid >> 2;
    int kg = (tid & 3) * 4;
    float4 v = *(const float4*)(W + (size_t)(nBase + wr) * NC + k0 + kg);
    Bs[(kg + 0) * BP2 + wr] = v.x;
    Bs[(kg + 1) * BP2 + wr] = v.y;
    Bs[(kg + 2) * BP2 + wr] = v.z;
    Bs[(kg + 3) * BP2 + wr] = v.w;
}

__device__ __forceinline__ void mma_tile(const float* As, const float* Bs,
                                         float c[8][4], int trow, int tcol) {
#pragma unroll
    for (int k = 0; k < BK; ++k) {
        float4 a0 = *(const float4*)(As + k * AP + trow * 8);
        float4 a1 = *(const float4*)(As + k * AP + trow * 8 + 4);
        float4 b0 = *(const float4*)(Bs + k * BP2 + tcol * 4);
        float a[8] = {a0.x, a0.y, a0.z, a0.w, a1.x, a1.y, a1.z, a1.w};
        float b[4] = {b0.x, b0.y, b0.z, b0.w};
#pragma unroll
        for (int i = 0; i < 8; ++i)
#pragma unroll
            for (int j = 0; j < 4; ++j)
                c[i][j] += a[i] * b[j];
    }
}

// ---------------------------------------------------------------------------
// K0: zero accumulators
// ---------------------------------------------------------------------------
__global__ void k_zero() {
    int i = blockIdx.x * blockDim.x + threadIdx.x;
    if (i < NB * NH * NG * ND) g_acc[i] = 0.0f;
    if (i < NB * NH * NG) g_cnt[i] = 0;
}

// ---------------------------------------------------------------------------
// K1: q projection -> g_qT[bh][d][n] (fp32, tiny)
// ---------------------------------------------------------------------------
__global__ void __launch_bounds__(256) k_qproj(const float* __restrict__ query,
                                               const float* __restrict__ Wq) {
    __shared__ float As[BK * AP];
    __shared__ float Bs[BK * BP2];
    int tid = threadIdx.x;
    int trow = tid >> 4, tcol = tid & 15;
    int mBase = blockIdx.x * BM;
    int h = blockIdx.y;

    float c[8][4] = {};
    for (int k0 = 0; k0 < NC; k0 += BK) {
        load_A_tile(query, mBase, k0, As, tid);
        load_B_tile(Wq, h * 64, k0, Bs, tid);
        __syncthreads();
        mma_tile(As, Bs, c, trow, tcol);
        __syncthreads();
    }
#pragma unroll
    for (int i = 0; i < 8; ++i) {
        int m = mBase + trow * 8 + i;
        int b = m >> 6, n = m & 63;
#pragma unroll
        for (int j = 0; j < 4; ++j) {
            int d = tcol * 4 + j;
            g_qT[((b * NH + h) * ND + d) * NG + n] = c[i][j];
        }
    }
}

// ---------------------------------------------------------------------------
// K2: kp = key@Wk^T via 3xTF32 (pipelined) + fp32 score/argmax epilogue
// (numerically identical to the proven R3 kernel)
// ---------------------------------------------------------------------------
__global__ void __launch_bounds__(256) k2_assign(const float* __restrict__ key,
                                                 const float* __restrict__ Wk) {
    __shared__ __align__(16) union {
        struct { float Ah[2 * ASZ]; float Al[2 * ASZ];
                 float Bh[2 * BSZ]; float Bl[2 * BSZ]; } g;   // 61440 B
        struct { float Kp[128 * 64]; float Qs[64 * 64]; } e;  // 49152 B
    } sm;

    int tid = threadIdx.x;
    int lane = tid & 31;
    int warpM = (tid >> 5) & 3;
    int warpN = tid >> 7;
    int grp = lane >> 2, qd = lane & 3;

    int mBase = blockIdx.x * 128;
    int b = mBase >> 12;
    int sBase = mBase & (NS - 1);
    int h = blockIdx.y;
    int bh = b * NH + h;

    float cs[2][4][4] = {};
    gemm_tf32_pipe<true>(key, Wk + (size_t)h * 64 * NC, mBase, cs,
                         sm.g.Ah, sm.g.Al, sm.g.Bh, sm.g.Bl, tid);

    __syncthreads();  // GEMM smem reads done before union repurpose

    // Stage kp accumulators to smem [s][d]
#pragma unroll
    for (int mi = 0; mi < 2; ++mi)
#pragma unroll
        for (int nj = 0; nj < 4; ++nj) {
            int row = warpM * 32 + mi * 16 + grp;
            int col = warpN * 32 + nj * 8 + 2 * qd;
            *(float2*)&sm.e.Kp[row * 64 + col] =
                make_float2(cs[mi][nj][0], cs[mi][nj][1]);
            *(float2*)&sm.e.Kp[(row + 8) * 64 + col] =
                make_float2(cs[mi][nj][2], cs[mi][nj][3]);
        }
    // Load q^T tile [d][n]
    {
        const float* qsrc = g_qT + (size_t)bh * ND * NG;
#pragma unroll
        for (int r = 0; r < 4; ++r) {
            int off = (tid + 256 * r) * 4;
            *(float4*)&sm.e.Qs[off] = *(const float4*)&qsrc[off];
        }
    }
    __syncthreads();

    // scores[128 s][64 n] in fp32 (same association as reference: dot over d)
    int tr = tid >> 4, tc = tid & 15;
    float acc2[8][4] = {};
#pragma unroll 8
    for (int d = 0; d < 64; ++d) {
        float4 q4 = *(const float4*)&sm.e.Qs[d * 64 + tc * 4];
#pragma unroll
        for (int i = 0; i < 8; ++i) {
            float a = sm.e.Kp[(tr * 8 + i) * 64 + d];
            acc2[i][0] += a * q4.x;
            acc2[i][1] += a * q4.y;
            acc2[i][2] += a * q4.z;
            acc2[i][3] += a * q4.w;
        }
    }
#pragma unroll
    for (int i = 0; i < 8; ++i) {
        float mv = acc2[i][0];
        int mi = tc * 4;
#pragma unroll
        for (int j = 1; j < 4; ++j)
            if (acc2[i][j] > mv) { mv = acc2[i][j]; mi = tc * 4 + j; }
#pragma unroll
        for (int off = 8; off >= 1; off >>= 1) {
            float ov = __shfl_down_sync(0xffffffffu, mv, off, 16);
            int   oi = __shfl_down_sync(0xffffffffu, mi, off, 16);
            if (ov > mv || (ov == mv && oi < mi)) { mv = ov; mi = oi; }
        }
        if (tc == 0) {
            g_idx[bh * NS + sBase + tr * 8 + i] = mi;
            atomicAdd(&g_cnt[bh * NG + mi], 1);
        }
    }
}

// ---------------------------------------------------------------------------
// K3: vp = key@Wv^T via 1xTF32 (pipelined) + fused atomic scatter
// ---------------------------------------------------------------------------
__global__ void __launch_bounds__(256) k3_scatter(const float* __restrict__ key,
                                                  const float* __restrict__ Wv) {
    __shared__ __align__(16) float Ah[2 * ASZ];
    __shared__ __align__(16) float Bvh[2 * BSZ];

    int tid = threadIdx.x;
    int lane = tid & 31;
    int warpM = (tid >> 5) & 3;
    int warpN = tid >> 7;
    int grp = lane >> 2, qd = lane & 3;

    int mBase = blockIdx.x * 128;
    int b = mBase >> 12;
    int sBase = mBase & (NS - 1);
    int h = blockIdx.y;
    int bh = b * NH + h;

    float cv[2][4][4] = {};
    gemm_tf32_pipe<false>(key, Wv + (size_t)h * 64 * NC, mBase, cv,
                          Ah, nullptr, Bvh, nullptr, tid);

    // scatter vp using g_idx
#pragma unroll
    for (int mi = 0; mi < 2; ++mi) {
        int s0 = sBase + warpM * 32 + mi * 16 + grp;
        int n0 = g_idx[bh * NS + s0];
        int n1 = g_idx[bh * NS + s0 + 8];
#pragma unroll
        for (int nj = 0; nj < 4; ++nj) {
            int d = warpN * 32 + nj * 8 + 2 * qd;
            float* p0 = &g_acc[(bh * NG + n0) * ND + d];
            atomicAdd(p0,     cv[mi][nj][0]);
            atomicAdd(p0 + 1, cv[mi][nj][1]);
            float* p1 = &g_acc[(bh * NG + n1) * ND + d];
            atomicAdd(p1,     cv[mi][nj][2]);
            atomicAdd(p1 + 1, cv[mi][nj][3]);
        }
    }
}

// ---------------------------------------------------------------------------
// K4: normalize + out = tmp @ Wp^T + bp (fp32, tiny)
// ---------------------------------------------------------------------------
__global__ void __launch_bounds__(256) k_finalize(const float* __restrict__ Wp,
                                                  const float* __restrict__ bp,
                                                  float* __restrict__ out) {
    __shared__ float As[BK * AP];
    __shared__ float Bs[BK * BP2];
    int tid = threadIdx.x;
    int trow = tid >> 4, tcol = tid & 15;
    int mBase = blockIdx.x * BM;
    int nBase = blockIdx.y * BN;

    float c[8][4] = {};
    for (int k0 = 0; k0 < NC; k0 += BK) {
#pragma unroll
        for (int l = 0; l < 2; ++l) {
            int lin = tid * 2 + l;
            int m = lin >> 2;
            int kg = (lin & 3) * 4;
            int gm = mBase + m;
            int b = gm >> 6, n = gm & 63;
            int cc = k0 + kg;
            int h = cc >> 6, d = cc & 63;
            int bh = b * NH + h;
            float inv = 1.0f / (float)(g_cnt[bh * NG + n] + 1);
            float4 v = *(const float4*)&g_acc[(bh * NG + n) * ND + d];
            As[(kg + 0) * AP + m] = v.x * inv;
            As[(kg + 1) * AP + m] = v.y * inv;
            As[(kg + 2) * AP + m] = v.z * inv;
            As[(kg + 3) * AP + m] = v.w * inv;
        }
        load_B_tile(Wp, nBase, k0, Bs, tid);
        __syncthreads();
        mma_tile(As, Bs, c, trow, tcol);
        __syncthreads();
    }

    float4 bias = *(const float4*)&bp[nBase + tcol * 4];
#pragma unroll
    for (int i = 0; i < 8; ++i) {
        int m = mBase + trow * 8 + i;
        float4 v = make_float4(c[i][0] + bias.x, c[i][1] + bias.y,
                               c[i][2] + bias.z, c[i][3] + bias.w);
        *(float4*)&out[(size_t)m * NC + nBase + tcol * 4] = v;
    }
}

// ---------------------------------------------------------------------------
extern "C" void kernel_launch(void* const* d_in, const int* in_sizes, int n_in,
                              void* d_out, int out_size) {
    const float* query = (const float*)d_in[0];
    const float* key   = (const float*)d_in[1];
    const float* Wq    = (const float*)d_in[2];
    const float* Wk    = (const float*)d_in[3];
    const float* Wv    = (const float*)d_in[4];
    const float* Wp    = (const float*)d_in[5];
    const float* bp    = (const float*)d_in[6];
    float* out = (float*)d_out;

    k_zero<<<(NB * NH * NG * ND + 255) / 256, 256>>>();
    k_qproj<<<dim3(8, 6), 256>>>(query, Wq);
    k2_assign<<<dim3((NB * NS) / 128, NH), 256>>>(key, Wk);
    k3_scatter<<<dim3((NB * NS) / 128, NH), 256>>>(key, Wv);
    k_finalize<<<dim3(8, 6), 256>>>(Wp, bp, out);
}